// round 2
// baseline (speedup 1.0000x reference)
#include <cuda_runtime.h>
#include <cuda_fp16.h>
#include <stdint.h>

// ---------------- scratch (__device__ globals; no allocations anywhere) ----
__device__ __half g_xh [4096u * 2048u];   // x transposed: row (b,p), K=2048 contiguous, fp16
__device__ __half g_w1t[512u  * 2048u];   // Wg1 as [n][k] fp16 (n<256: W1a col, n>=256: W1b col)
__device__ __half g_w2t[256 * 256];       // Wg2^T fp16 [n][k]
__device__ __half g_w3t[256 * 256];
__device__ __half g_w4t[256 * 256];
__device__ __half g_AB [4096u * 512u];    // GEMM1 out: [ (b,p) ][ 512 ] (A | B)
__device__ __half g_h1 [131072u * 256u];  // ping
__device__ __half g_h2 [131072u * 256u];  // pong
__device__ float  g_part[1024 * 256];     // partial sums
__device__ float  g_xg [128 * 256];
__device__ float  g_xf [128 * 256];
__device__ float  g_y1 [128 * 256];

// ---------------- transpose + fp32->fp16 convert: out[c][r] = in[r][c] -----
// R, C multiples of 32. blockIdx.z batches (stride R*C on both sides).
__global__ void k_transpose(const float* __restrict__ in, __half* __restrict__ out,
                            int R, int C)
{
    __shared__ float t[32][33];
    const float* inb = in + (size_t)blockIdx.z * R * C;
    __half* outb     = out + (size_t)blockIdx.z * R * C;
    int r0 = blockIdx.y * 32, c0 = blockIdx.x * 32;
    for (int i = threadIdx.y; i < 32; i += 8)
        t[i][threadIdx.x] = inb[(size_t)(r0 + i) * C + c0 + threadIdx.x];
    __syncthreads();
    for (int i = threadIdx.y; i < 32; i += 8)
        outb[(size_t)(c0 + i) * R + r0 + threadIdx.x] = __float2half(t[threadIdx.x][i]);
}

// ---------------- fp16 HMMA GEMM: C[M,N] = A[M,K] * Bt[N,K]^T ---------------
// BM=128, BN=128, BK=32, 256 threads, warp tile 32x64, mma m16n8k16 f32 accum.
// M % 128 == 0, N % 128 == 0, K % 32 == 0 (all shapes here satisfy this).
template<int BIASRELU>
__global__ __launch_bounds__(256) void k_gemm(const __half* __restrict__ A,
                                              const __half* __restrict__ Bt,
                                              const float*  __restrict__ bias,
                                              __half* __restrict__ C,
                                              int M, int N, int K)
{
    __shared__ __half sA[128][40];
    __shared__ __half sB[128][40];
    const int m0 = blockIdx.y * 128, n0 = blockIdx.x * 128;
    const int tid  = threadIdx.x;
    const int warp = tid >> 5, lane = tid & 31;
    const int wm0 = (warp & 3) * 32;          // warp row offset in CTA tile
    const int wn0 = (warp >> 2) * 64;         // warp col offset
    const int g  = lane >> 2;                 // 0..7
    const int c2 = (lane & 3) * 2;            // 0,2,4,6

    float acc[2][8][4];
    #pragma unroll
    for (int mt = 0; mt < 2; mt++)
        #pragma unroll
        for (int nt = 0; nt < 8; nt++)
            #pragma unroll
            for (int q = 0; q < 4; q++) acc[mt][nt][q] = 0.f;

    const __half* Ag = A  + (size_t)m0 * K;
    const __half* Bg = Bt + (size_t)n0 * K;
    const int lrow = tid >> 2;                // 0..63
    const int lc4  = tid & 3;                 // 0..3 (uint4 column within 32-half row)

    for (int k0 = 0; k0 < K; k0 += 32) {
        *(uint4*)&sA[lrow     ][lc4 * 8] = *(const uint4*)(Ag + (size_t)(lrow     ) * K + k0 + lc4 * 8);
        *(uint4*)&sA[lrow + 64][lc4 * 8] = *(const uint4*)(Ag + (size_t)(lrow + 64) * K + k0 + lc4 * 8);
        *(uint4*)&sB[lrow     ][lc4 * 8] = *(const uint4*)(Bg + (size_t)(lrow     ) * K + k0 + lc4 * 8);
        *(uint4*)&sB[lrow + 64][lc4 * 8] = *(const uint4*)(Bg + (size_t)(lrow + 64) * K + k0 + lc4 * 8);
        __syncthreads();

        #pragma unroll
        for (int kk = 0; kk < 32; kk += 16) {
            uint32_t af[2][4], bf[8][2];
            #pragma unroll
            for (int mt = 0; mt < 2; mt++) {
                int rb = wm0 + mt * 16;
                af[mt][0] = *(const uint32_t*)&sA[rb + g    ][kk + c2];
                af[mt][1] = *(const uint32_t*)&sA[rb + g + 8][kk + c2];
                af[mt][2] = *(const uint32_t*)&sA[rb + g    ][kk + 8 + c2];
                af[mt][3] = *(const uint32_t*)&sA[rb + g + 8][kk + 8 + c2];
            }
            #pragma unroll
            for (int nt = 0; nt < 8; nt++) {
                int nb = wn0 + nt * 8 + g;
                bf[nt][0] = *(const uint32_t*)&sB[nb][kk + c2];
                bf[nt][1] = *(const uint32_t*)&sB[nb][kk + 8 + c2];
            }
            #pragma unroll
            for (int mt = 0; mt < 2; mt++)
                #pragma unroll
                for (int nt = 0; nt < 8; nt++)
                    asm volatile(
                        "mma.sync.aligned.m16n8k16.row.col.f32.f16.f16.f32 "
                        "{%0,%1,%2,%3}, {%4,%5,%6,%7}, {%8,%9}, {%0,%1,%2,%3};\n"
                        : "+f"(acc[mt][nt][0]), "+f"(acc[mt][nt][1]),
                          "+f"(acc[mt][nt][2]), "+f"(acc[mt][nt][3])
                        : "r"(af[mt][0]), "r"(af[mt][1]), "r"(af[mt][2]), "r"(af[mt][3]),
                          "r"(bf[nt][0]), "r"(bf[nt][1]));
        }
        __syncthreads();
    }

    // epilogue: (+bias, relu) -> fp16
    #pragma unroll
    for (int mt = 0; mt < 2; mt++) {
        int row = m0 + wm0 + mt * 16 + g;
        #pragma unroll
        for (int nt = 0; nt < 8; nt++) {
            int col = n0 + wn0 + nt * 8 + c2;
            float v0 = acc[mt][nt][0], v1 = acc[mt][nt][1];
            float v2 = acc[mt][nt][2], v3 = acc[mt][nt][3];
            if (BIASRELU) {
                float b0 = bias[col], b1 = bias[col + 1];
                v0 = fmaxf(v0 + b0, 0.f); v1 = fmaxf(v1 + b1, 0.f);
                v2 = fmaxf(v2 + b0, 0.f); v3 = fmaxf(v3 + b1, 0.f);
            }
            *(__half2*)&C[(size_t)row       * N + col] = __floats2half2_rn(v0, v1);
            *(__half2*)&C[(size_t)(row + 8) * N + col] = __floats2half2_rn(v2, v3);
        }
    }
}

// ---------------- expand: h1[(b,i,j),d] = relu(A[b,j,d] + B[b,i,d] + bg1[d]) -
__global__ void k_expand(const float* __restrict__ bg1)
{
    int gid = blockIdx.x * blockDim.x + threadIdx.x;  // over 16,777,216 half2
    int d2 = gid & 127;
    int r  = gid >> 7;
    int b  = r >> 10;
    int i  = (r >> 5) & 31;
    int j  = r & 31;
    const __half2* Ar = (const __half2*)(g_AB + (size_t)(b * 32 + j) * 512);
    const __half2* Br = (const __half2*)(g_AB + (size_t)(b * 32 + i) * 512 + 256);
    float2 a  = __half22float2(Ar[d2]);
    float2 bb = __half22float2(Br[d2]);
    float v0 = fmaxf(a.x + bb.x + bg1[d2 * 2    ], 0.f);
    float v1 = fmaxf(a.y + bb.y + bg1[d2 * 2 + 1], 0.f);
    ((__half2*)g_h1)[gid] = __floats2half2_rn(v0, v1);
}

// ---------------- two-stage sum over the 1024 pairs per batch ---------------
__global__ void k_sum_partial()
{
    int b = blockIdx.x, s = blockIdx.y, d = threadIdx.x;
    const __half* base = g_h2 + (size_t)(b * 1024 + s * 128) * 256 + d;
    float acc = 0.f;
    #pragma unroll 8
    for (int r = 0; r < 128; r++) acc += __half2float(base[(size_t)r * 256]);
    g_part[(size_t)(b * 8 + s) * 256 + d] = acc;
}

__global__ void k_sum_final()
{
    int b = blockIdx.x, d = threadIdx.x;
    float acc = 0.f;
    #pragma unroll
    for (int s = 0; s < 8; s++) acc += g_part[(size_t)(b * 8 + s) * 256 + d];
    g_xg[b * 256 + d] = acc;
}

// ---------------- fp32 tail (tiny: 128 rows) --------------------------------
template<int RELU>
__global__ void k_tail(const float* __restrict__ X, const float* __restrict__ W,
                       const float* __restrict__ bias, float* __restrict__ Y,
                       int K, int N)
{
    __shared__ float sx[256];
    int row = blockIdx.x, n = threadIdx.x;
    for (int k = n; k < K; k += blockDim.x) sx[k] = X[(size_t)row * K + k];
    __syncthreads();
    float acc = bias[n];
    for (int k = 0; k < K; k++) acc = fmaf(sx[k], W[(size_t)k * N + n], acc);
    if (RELU) acc = fmaxf(acc, 0.f);
    Y[(size_t)row * N + n] = acc;
}

// ---------------- host ------------------------------------------------------
extern "C" void kernel_launch(void* const* d_in, const int* in_sizes, int n_in,
                              void* d_out, int out_size)
{
    const float* x    = (const float*)d_in[0];
    const float* Wg1  = (const float*)d_in[1];
    const float* bg1  = (const float*)d_in[2];
    const float* Wg2  = (const float*)d_in[3];
    const float* bg2  = (const float*)d_in[4];
    const float* Wg3  = (const float*)d_in[5];
    const float* bg3  = (const float*)d_in[6];
    const float* Wg4  = (const float*)d_in[7];
    const float* bg4  = (const float*)d_in[8];
    const float* Wf1  = (const float*)d_in[9];
    const float* bf1  = (const float*)d_in[10];
    const float* Wfc2 = (const float*)d_in[11];
    const float* bfc2 = (const float*)d_in[12];
    const float* Wfc3 = (const float*)d_in[13];
    const float* bfc3 = (const float*)d_in[14];
    float* out = (float*)d_out;

    __half *xh, *w1t, *w2t, *w3t, *w4t, *AB, *h1, *h2;
    float *xg, *xf, *y1;
    cudaGetSymbolAddress((void**)&xh,  g_xh);
    cudaGetSymbolAddress((void**)&w1t, g_w1t);
    cudaGetSymbolAddress((void**)&w2t, g_w2t);
    cudaGetSymbolAddress((void**)&w3t, g_w3t);
    cudaGetSymbolAddress((void**)&w4t, g_w4t);
    cudaGetSymbolAddress((void**)&AB,  g_AB);
    cudaGetSymbolAddress((void**)&h1,  g_h1);
    cudaGetSymbolAddress((void**)&h2,  g_h2);
    cudaGetSymbolAddress((void**)&xg,  g_xg);
    cudaGetSymbolAddress((void**)&xf,  g_xf);
    cudaGetSymbolAddress((void**)&y1,  g_y1);

    dim3 tb(32, 8);
    // x (per-batch 2048x32) -> xh[(b,p)][c]
    k_transpose<<<dim3(1, 64, 128), tb>>>(x, xh, 2048, 32);
    // Wg1 halves -> w1t [512][2048]
    k_transpose<<<dim3(8, 64, 1), tb>>>(Wg1,              w1t,               2048, 256);
    k_transpose<<<dim3(8, 64, 1), tb>>>(Wg1 + 2048 * 256, w1t + 256 * 2048,  2048, 256);
    // layer weights -> [n][k]
    k_transpose<<<dim3(8, 8, 1), tb>>>(Wg2, w2t, 256, 256);
    k_transpose<<<dim3(8, 8, 1), tb>>>(Wg3, w3t, 256, 256);
    k_transpose<<<dim3(8, 8, 1), tb>>>(Wg4, w4t, 256, 256);

    // GEMM1: AB[4096,512] = xh @ w1t^T   (no bias/relu)
    k_gemm<0><<<dim3(4, 32), 256>>>(xh, w1t, nullptr, AB, 4096, 512, 2048);

    // expand -> h1 [131072, 256]
    k_expand<<<65536, 256>>>(bg1);

    // three pairwise layers (bias + relu fused)
    k_gemm<1><<<dim3(2, 1024), 256>>>(h1, w2t, bg2, h2, 131072, 256, 256);
    k_gemm<1><<<dim3(2, 1024), 256>>>(h2, w3t, bg3, h1, 131072, 256, 256);
    k_gemm<1><<<dim3(2, 1024), 256>>>(h1, w4t, bg4, h2, 131072, 256, 256);

    // sum over (i,j) -> xg [128,256] fp32
    k_sum_partial<<<dim3(128, 8), 256>>>();
    k_sum_final<<<128, 256>>>();

    // fp32 tail
    k_tail<1><<<128, 256>>>(xg, Wf1,  bf1,  xf,  256, 256);
    k_tail<1><<<128, 256>>>(xf, Wfc2, bfc2, y1,  256, 256);
    k_tail<0><<<128, 128>>>(y1, Wfc3, bfc3, out, 256, 128);
}

// round 3
// speedup vs baseline: 1.3360x; 1.3360x over previous
#include <cuda_runtime.h>
#include <cuda_fp16.h>
#include <stdint.h>

// ---------------- scratch (__device__ globals; no allocations anywhere) ----
__device__ __half g_xh [4096u * 2048u];   // x transposed: row (b,p), K=2048 contiguous, fp16
__device__ __half g_w1t[512u  * 2048u];   // Wg1 as [n][k] fp16
__device__ __half g_w2t[256 * 256];       // Wg2^T fp16 [n][k]
__device__ __half g_w3t[256 * 256];
__device__ __half g_w4t[256 * 256];
__device__ __half g_AB [4096u * 512u];    // GEMM1 out: [(b,p)][512] (A | B)
__device__ float  g_part[1024 * 256];     // per-CTA partial column sums
__device__ float  g_xg [128 * 256];
__device__ float  g_xf [128 * 256];
__device__ float  g_y1 [128 * 256];

// ---------------- transpose + fp32->fp16 convert: out[c][r] = in[r][c] -----
__global__ void k_transpose(const float* __restrict__ in, __half* __restrict__ out,
                            int R, int C)
{
    __shared__ float t[32][33];
    const float* inb = in + (size_t)blockIdx.z * R * C;
    __half* outb     = out + (size_t)blockIdx.z * R * C;
    int r0 = blockIdx.y * 32, c0 = blockIdx.x * 32;
    for (int i = threadIdx.y; i < 32; i += 8)
        t[i][threadIdx.x] = inb[(size_t)(r0 + i) * C + c0 + threadIdx.x];
    __syncthreads();
    for (int i = threadIdx.y; i < 32; i += 8)
        outb[(size_t)(c0 + i) * R + r0 + threadIdx.x] = __float2half(t[threadIdx.x][i]);
}

// ---------------- fp16 HMMA GEMM (used for GEMM1 only) ---------------------
__global__ __launch_bounds__(256) void k_gemm(const __half* __restrict__ A,
                                              const __half* __restrict__ Bt,
                                              __half* __restrict__ C,
                                              int M, int N, int K)
{
    __shared__ __half sA[128][40];
    __shared__ __half sB[128][40];
    const int m0 = blockIdx.y * 128, n0 = blockIdx.x * 128;
    const int tid  = threadIdx.x;
    const int warp = tid >> 5, lane = tid & 31;
    const int wm0 = (warp & 3) * 32;
    const int wn0 = (warp >> 2) * 64;
    const int g  = lane >> 2;
    const int c2 = (lane & 3) * 2;

    float acc[2][8][4];
    #pragma unroll
    for (int mt = 0; mt < 2; mt++)
        #pragma unroll
        for (int nt = 0; nt < 8; nt++)
            #pragma unroll
            for (int q = 0; q < 4; q++) acc[mt][nt][q] = 0.f;

    const __half* Ag = A  + (size_t)m0 * K;
    const __half* Bg = Bt + (size_t)n0 * K;
    const int lrow = tid >> 2;
    const int lc4  = tid & 3;

    for (int k0 = 0; k0 < K; k0 += 32) {
        *(uint4*)&sA[lrow     ][lc4 * 8] = *(const uint4*)(Ag + (size_t)(lrow     ) * K + k0 + lc4 * 8);
        *(uint4*)&sA[lrow + 64][lc4 * 8] = *(const uint4*)(Ag + (size_t)(lrow + 64) * K + k0 + lc4 * 8);
        *(uint4*)&sB[lrow     ][lc4 * 8] = *(const uint4*)(Bg + (size_t)(lrow     ) * K + k0 + lc4 * 8);
        *(uint4*)&sB[lrow + 64][lc4 * 8] = *(const uint4*)(Bg + (size_t)(lrow + 64) * K + k0 + lc4 * 8);
        __syncthreads();

        #pragma unroll
        for (int kk = 0; kk < 32; kk += 16) {
            uint32_t af[2][4], bf[8][2];
            #pragma unroll
            for (int mt = 0; mt < 2; mt++) {
                int rb = wm0 + mt * 16;
                af[mt][0] = *(const uint32_t*)&sA[rb + g    ][kk + c2];
                af[mt][1] = *(const uint32_t*)&sA[rb + g + 8][kk + c2];
                af[mt][2] = *(const uint32_t*)&sA[rb + g    ][kk + 8 + c2];
                af[mt][3] = *(const uint32_t*)&sA[rb + g + 8][kk + 8 + c2];
            }
            #pragma unroll
            for (int nt = 0; nt < 8; nt++) {
                int nb = wn0 + nt * 8 + g;
                bf[nt][0] = *(const uint32_t*)&sB[nb][kk + c2];
                bf[nt][1] = *(const uint32_t*)&sB[nb][kk + 8 + c2];
            }
            #pragma unroll
            for (int mt = 0; mt < 2; mt++)
                #pragma unroll
                for (int nt = 0; nt < 8; nt++)
                    asm volatile(
                        "mma.sync.aligned.m16n8k16.row.col.f32.f16.f16.f32 "
                        "{%0,%1,%2,%3}, {%4,%5,%6,%7}, {%8,%9}, {%0,%1,%2,%3};\n"
                        : "+f"(acc[mt][nt][0]), "+f"(acc[mt][nt][1]),
                          "+f"(acc[mt][nt][2]), "+f"(acc[mt][nt][3])
                        : "r"(af[mt][0]), "r"(af[mt][1]), "r"(af[mt][2]), "r"(af[mt][3]),
                          "r"(bf[nt][0]), "r"(bf[nt][1]));
        }
        __syncthreads();
    }

    #pragma unroll
    for (int mt = 0; mt < 2; mt++) {
        int row = m0 + wm0 + mt * 16 + g;
        #pragma unroll
        for (int nt = 0; nt < 8; nt++) {
            int col = n0 + wn0 + nt * 8 + c2;
            *(__half2*)&C[(size_t)row       * N + col] = __floats2half2_rn(acc[mt][nt][0], acc[mt][nt][1]);
            *(__half2*)&C[(size_t)(row + 8) * N + col] = __floats2half2_rn(acc[mt][nt][2], acc[mt][nt][3]);
        }
    }
}

// ---------------- fused pairwise stage --------------------------------------
// One CTA = 128 rows x 256 feat. expand -> L2 -> L3 -> L4 -> column sum.
// smem: act[128][264] (67584 B) + W chunks [2][256][40] (40960 B) + col[2][256] (2048 B)
static const int SMEM_FUSED = 128*264*2 + 2*256*40*2 + 2*256*4;

__device__ __forceinline__ void prefetch_w(const __half* __restrict__ Wt, int kc,
                                           __half (*sWbuf)[40], int tid)
{
    #pragma unroll
    for (int it = 0; it < 4; it++) {
        int idx = it * 256 + tid;
        int n = idx >> 2, c4 = idx & 3;
        const __half* src = Wt + n * 256 + kc * 32 + c4 * 8;
        unsigned dst = (unsigned)__cvta_generic_to_shared(&sWbuf[n][c4 * 8]);
        asm volatile("cp.async.cg.shared.global [%0], [%1], 16;\n" :: "r"(dst), "l"(src));
    }
    asm volatile("cp.async.commit_group;\n");
}

__global__ __launch_bounds__(256, 1) void k_fused(const float* __restrict__ bg1,
                                                  const float* __restrict__ bg2,
                                                  const float* __restrict__ bg3,
                                                  const float* __restrict__ bg4)
{
    extern __shared__ char smem[];
    __half (*sAct)[264]     = (__half(*)[264])smem;
    __half (*sW)[256][40]   = (__half(*)[256][40])(smem + 128*264*2);
    float*  sCol            = (float*)(smem + 128*264*2 + 2*256*40*2);

    const int tid  = threadIdx.x;
    const int warp = tid >> 5, lane = tid & 31;
    const int g    = lane >> 2, c2 = (lane & 3) * 2;
    const int wm0  = (warp & 1) * 64;
    const int wn0  = (warp >> 1) * 64;
    const int ct   = blockIdx.x;
    const int b    = ct >> 3;
    const int i0   = (ct & 7) * 4;

    const __half* wts[3]    = {g_w2t, g_w3t, g_w4t};
    const float*  biases[3] = {bg2, bg3, bg4};

    // kick off layer-0 weight chunk 0 load, overlapping the build stage
    prefetch_w(wts[0], 0, sW[0], tid);

    // ---- build stage: act[m][d] = relu(A[b,j,d] + B[b,i,d] + bg1[d]) ----
    {
        int m = tid >> 1, half = tid & 1;
        int i = i0 + (m >> 5), j = m & 31;
        const __half2* Ar = (const __half2*)g_AB + (size_t)(b * 32 + j) * 256 + half * 64;
        const __half2* Br = (const __half2*)g_AB + (size_t)(b * 32 + i) * 256 + 128 + half * 64;
        const float2*  bb = (const float2*)bg1 + half * 64;
        __half2* dst = (__half2*)&sAct[m][half * 128];
        #pragma unroll 8
        for (int cc = 0; cc < 64; cc++) {
            float2 a = __half22float2(Ar[cc]);
            float2 e = __half22float2(Br[cc]);
            float2 bi = bb[cc];
            dst[cc] = __floats2half2_rn(fmaxf(a.x + e.x + bi.x, 0.f),
                                        fmaxf(a.y + e.y + bi.y, 0.f));
        }
    }

    // ---- three GEMM layers, act resident in smem ----
    for (int L = 0; L < 3; L++) {
        const __half* Wt  = wts[L];
        const float* bias = biases[L];

        float acc[4][8][4];
        #pragma unroll
        for (int mt = 0; mt < 4; mt++)
            #pragma unroll
            for (int nt = 0; nt < 8; nt++)
                #pragma unroll
                for (int q = 0; q < 4; q++) acc[mt][nt][q] = 0.f;

        for (int kc = 0; kc < 8; kc++) {
            asm volatile("cp.async.wait_group 0;\n" ::: "memory");
            __syncthreads();
            if (kc < 7)       prefetch_w(Wt,       kc + 1, sW[(kc + 1) & 1], tid);
            else if (L < 2)   prefetch_w(wts[L+1], 0,      sW[0],            tid);
            const int buf = kc & 1;

            #pragma unroll
            for (int kk = 0; kk < 32; kk += 16) {
                const int kbase = kc * 32 + kk;
                uint32_t af[4][4], bf[8][2];
                #pragma unroll
                for (int mt = 0; mt < 4; mt++) {
                    int rb = wm0 + mt * 16;
                    af[mt][0] = *(const uint32_t*)&sAct[rb + g    ][kbase + c2];
                    af[mt][1] = *(const uint32_t*)&sAct[rb + g + 8][kbase + c2];
                    af[mt][2] = *(const uint32_t*)&sAct[rb + g    ][kbase + 8 + c2];
                    af[mt][3] = *(const uint32_t*)&sAct[rb + g + 8][kbase + 8 + c2];
                }
                #pragma unroll
                for (int nt = 0; nt < 8; nt++) {
                    int nb = wn0 + nt * 8 + g;
                    bf[nt][0] = *(const uint32_t*)&sW[buf][nb][kk + c2];
                    bf[nt][1] = *(const uint32_t*)&sW[buf][nb][kk + 8 + c2];
                }
                #pragma unroll
                for (int mt = 0; mt < 4; mt++)
                    #pragma unroll
                    for (int nt = 0; nt < 8; nt++)
                        asm volatile(
                            "mma.sync.aligned.m16n8k16.row.col.f32.f16.f16.f32 "
                            "{%0,%1,%2,%3}, {%4,%5,%6,%7}, {%8,%9}, {%0,%1,%2,%3};\n"
                            : "+f"(acc[mt][nt][0]), "+f"(acc[mt][nt][1]),
                              "+f"(acc[mt][nt][2]), "+f"(acc[mt][nt][3])
                            : "r"(af[mt][0]), "r"(af[mt][1]), "r"(af[mt][2]), "r"(af[mt][3]),
                              "r"(bf[nt][0]), "r"(bf[nt][1]));
            }
        }
        __syncthreads();   // all warps done reading sAct for this layer

        if (L < 2) {
            // relu(acc + bias) -> back into sAct
            #pragma unroll
            for (int mt = 0; mt < 4; mt++) {
                int row = wm0 + mt * 16 + g;
                #pragma unroll
                for (int nt = 0; nt < 8; nt++) {
                    int col = wn0 + nt * 8 + c2;
                    float b0 = bias[col], b1 = bias[col + 1];
                    *(__half2*)&sAct[row    ][col] =
                        __floats2half2_rn(fmaxf(acc[mt][nt][0] + b0, 0.f),
                                          fmaxf(acc[mt][nt][1] + b1, 0.f));
                    *(__half2*)&sAct[row + 8][col] =
                        __floats2half2_rn(fmaxf(acc[mt][nt][2] + b0, 0.f),
                                          fmaxf(acc[mt][nt][3] + b1, 0.f));
                }
            }
            // next iteration's top-of-loop __syncthreads orders these stores
        } else {
            // relu(acc + bias) and reduce over this CTA's 128 rows -> sCol
            #pragma unroll
            for (int nt = 0; nt < 8; nt++) {
                int col = wn0 + nt * 8 + c2;
                float b0 = bias[col], b1 = bias[col + 1];
                float s0 = 0.f, s1 = 0.f;
                #pragma unroll
                for (int mt = 0; mt < 4; mt++) {
                    s0 += fmaxf(acc[mt][nt][0] + b0, 0.f) + fmaxf(acc[mt][nt][2] + b0, 0.f);
                    s1 += fmaxf(acc[mt][nt][1] + b1, 0.f) + fmaxf(acc[mt][nt][3] + b1, 0.f);
                }
                #pragma unroll
                for (int o = 4; o < 32; o <<= 1) {
                    s0 += __shfl_xor_sync(0xffffffffu, s0, o);
                    s1 += __shfl_xor_sync(0xffffffffu, s1, o);
                }
                if (lane < 4) {
                    sCol[(warp & 1) * 256 + wn0 + nt * 8 + lane * 2    ] = s0;
                    sCol[(warp & 1) * 256 + wn0 + nt * 8 + lane * 2 + 1] = s1;
                }
            }
            __syncthreads();
            g_part[(size_t)ct * 256 + tid] = sCol[tid] + sCol[256 + tid];
        }
    }
}

// ---------------- final sum over the 8 CTA partials per batch ---------------
__global__ void k_sum_final()
{
    int b = blockIdx.x, d = threadIdx.x;
    float acc = 0.f;
    #pragma unroll
    for (int s = 0; s < 8; s++) acc += g_part[(size_t)(b * 8 + s) * 256 + d];
    g_xg[b * 256 + d] = acc;
}

// ---------------- fp32 tail (tiny: 128 rows) --------------------------------
template<int RELU>
__global__ void k_tail(const float* __restrict__ X, const float* __restrict__ W,
                       const float* __restrict__ bias, float* __restrict__ Y,
                       int K, int N)
{
    __shared__ float sx[256];
    int row = blockIdx.x, n = threadIdx.x;
    for (int k = n; k < K; k += blockDim.x) sx[k] = X[(size_t)row * K + k];
    __syncthreads();
    float acc = bias[n];
    for (int k = 0; k < K; k++) acc = fmaf(sx[k], W[(size_t)k * N + n], acc);
    if (RELU) acc = fmaxf(acc, 0.f);
    Y[(size_t)row * N + n] = acc;
}

// ---------------- host ------------------------------------------------------
extern "C" void kernel_launch(void* const* d_in, const int* in_sizes, int n_in,
                              void* d_out, int out_size)
{
    const float* x    = (const float*)d_in[0];
    const float* Wg1  = (const float*)d_in[1];
    const float* bg1  = (const float*)d_in[2];
    const float* Wg2  = (const float*)d_in[3];
    const float* bg2  = (const float*)d_in[4];
    const float* Wg3  = (const float*)d_in[5];
    const float* bg3  = (const float*)d_in[6];
    const float* Wg4  = (const float*)d_in[7];
    const float* bg4  = (const float*)d_in[8];
    const float* Wf1  = (const float*)d_in[9];
    const float* bf1  = (const float*)d_in[10];
    const float* Wfc2 = (const float*)d_in[11];
    const float* bfc2 = (const float*)d_in[12];
    const float* Wfc3 = (const float*)d_in[13];
    const float* bfc3 = (const float*)d_in[14];
    float* out = (float*)d_out;

    __half *xh, *w1t, *w2t, *w3t, *w4t, *AB;
    float *xg, *xf, *y1;
    cudaGetSymbolAddress((void**)&xh,  g_xh);
    cudaGetSymbolAddress((void**)&w1t, g_w1t);
    cudaGetSymbolAddress((void**)&w2t, g_w2t);
    cudaGetSymbolAddress((void**)&w3t, g_w3t);
    cudaGetSymbolAddress((void**)&w4t, g_w4t);
    cudaGetSymbolAddress((void**)&AB,  g_AB);
    cudaGetSymbolAddress((void**)&xg,  g_xg);
    cudaGetSymbolAddress((void**)&xf,  g_xf);
    cudaGetSymbolAddress((void**)&y1,  g_y1);

    cudaFuncSetAttribute(k_fused, cudaFuncAttributeMaxDynamicSharedMemorySize, SMEM_FUSED);

    dim3 tb(32, 8);
    k_transpose<<<dim3(1, 64, 128), tb>>>(x, xh, 2048, 32);
    k_transpose<<<dim3(8, 64, 1), tb>>>(Wg1,              w1t,              2048, 256);
    k_transpose<<<dim3(8, 64, 1), tb>>>(Wg1 + 2048 * 256, w1t + 256 * 2048, 2048, 256);
    k_transpose<<<dim3(8, 8, 1), tb>>>(Wg2, w2t, 256, 256);
    k_transpose<<<dim3(8, 8, 1), tb>>>(Wg3, w3t, 256, 256);
    k_transpose<<<dim3(8, 8, 1), tb>>>(Wg4, w4t, 256, 256);

    // GEMM1: AB[4096,512] = xh @ w1t^T
    k_gemm<<<dim3(4, 32), 256>>>(xh, w1t, AB, 4096, 512, 2048);

    // fused expand + 3 layers + pair-sum
    k_fused<<<1024, 256, SMEM_FUSED>>>(bg1, bg2, bg3, bg4);

    k_sum_final<<<128, 256>>>();

    k_tail<1><<<128, 256>>>(xg, Wf1,  bf1,  xf,  256, 256);
    k_tail<1><<<128, 256>>>(xf, Wfc2, bfc2, y1,  256, 256);
    k_tail<0><<<128, 128>>>(y1, Wfc3, bfc3, out, 256, 128);
}

// round 4
// speedup vs baseline: 1.6178x; 1.2110x over previous
#include <cuda_runtime.h>
#include <cuda_fp16.h>
#include <stdint.h>

// ---------------- scratch (__device__ globals; no allocations anywhere) ----
__device__ __half g_xh [4096u * 2048u];   // x transposed: row (b,p), K=2048 contiguous, fp16
__device__ __half g_w1t[512u  * 2048u];   // Wg1 as [n][k] fp16
__device__ __half g_w2t[256 * 256];       // Wg2^T fp16 [n][k]
__device__ __half g_w3t[256 * 256];
__device__ __half g_w4t[256 * 256];
__device__ __half g_AB [4096u * 512u];    // GEMM1 out: [(b,p)][512] (A | B)
__device__ float  g_part[1024 * 256];     // per-CTA partial column sums
__device__ float  g_xf [128 * 256];
__device__ float  g_y1 [128 * 256];

__device__ __forceinline__ uint32_t cvta_s(const void* p) {
    return (uint32_t)__cvta_generic_to_shared(p);
}
__device__ __forceinline__ void ldsm_x4(uint32_t& r0, uint32_t& r1, uint32_t& r2, uint32_t& r3,
                                        uint32_t addr) {
    asm volatile("ldmatrix.sync.aligned.m8n8.x4.shared.b16 {%0,%1,%2,%3}, [%4];\n"
                 : "=r"(r0), "=r"(r1), "=r"(r2), "=r"(r3) : "r"(addr));
}
#define MMA16816(acc, af, b0, b1)                                              \
    asm volatile(                                                              \
        "mma.sync.aligned.m16n8k16.row.col.f32.f16.f16.f32 "                   \
        "{%0,%1,%2,%3}, {%4,%5,%6,%7}, {%8,%9}, {%0,%1,%2,%3};\n"              \
        : "+f"(acc[0]), "+f"(acc[1]), "+f"(acc[2]), "+f"(acc[3])               \
        : "r"(af[0]), "r"(af[1]), "r"(af[2]), "r"(af[3]), "r"(b0), "r"(b1))

// ---------------- transpose + fp32->fp16 convert: out[c][r] = in[r][c] -----
__global__ void k_transpose(const float* __restrict__ in, __half* __restrict__ out,
                            int R, int C)
{
    __shared__ float t[32][33];
    const float* inb = in + (size_t)blockIdx.z * R * C;
    __half* outb     = out + (size_t)blockIdx.z * R * C;
    int r0 = blockIdx.y * 32, c0 = blockIdx.x * 32;
    for (int i = threadIdx.y; i < 32; i += 8)
        t[i][threadIdx.x] = inb[(size_t)(r0 + i) * C + c0 + threadIdx.x];
    __syncthreads();
    for (int i = threadIdx.y; i < 32; i += 8)
        outb[(size_t)(c0 + i) * R + r0 + threadIdx.x] = __float2half(t[threadIdx.x][i]);
}

// transpose the three 256x256 layer weights in one launch (z selects which)
__global__ void k_transpose_w234(const float* __restrict__ W2,
                                 const float* __restrict__ W3,
                                 const float* __restrict__ W4)
{
    __shared__ float t[32][33];
    const float* src[3] = {W2, W3, W4};
    __half* dst[3] = {g_w2t, g_w3t, g_w4t};
    const float* inb = src[blockIdx.z];
    __half* outb     = dst[blockIdx.z];
    int r0 = blockIdx.y * 32, c0 = blockIdx.x * 32;
    for (int i = threadIdx.y; i < 32; i += 8)
        t[i][threadIdx.x] = inb[(size_t)(r0 + i) * 256 + c0 + threadIdx.x];
    __syncthreads();
    for (int i = threadIdx.y; i < 32; i += 8)
        outb[(size_t)(c0 + i) * 256 + r0 + threadIdx.x] = __float2half(t[threadIdx.x][i]);
}

// ---------------- GEMM1: pipelined fp16 HMMA, BM=128 BN=128 BK=64 ----------
// C[M,N] = A[M,K] * Bt[N,K]^T ; dynamic smem, 2-stage cp.async.
static const int G1_SMEM = 2 * (128 * 72 * 2) * 2;   // 73728 B

__device__ __forceinline__ void g1_issue(const __half* __restrict__ Ag,
                                         const __half* __restrict__ Bg,
                                         __half (*sA)[72], __half (*sB)[72],
                                         int K, int k0, int tid)
{
    #pragma unroll
    for (int it = 0; it < 4; it++) {
        int idx = it * 256 + tid;
        int row = idx >> 3, c8 = (idx & 7) * 8;
        asm volatile("cp.async.cg.shared.global [%0], [%1], 16;\n"
                     :: "r"(cvta_s(&sA[row][c8])), "l"(Ag + (size_t)row * K + k0 + c8));
        asm volatile("cp.async.cg.shared.global [%0], [%1], 16;\n"
                     :: "r"(cvta_s(&sB[row][c8])), "l"(Bg + (size_t)row * K + k0 + c8));
    }
    asm volatile("cp.async.commit_group;\n");
}

__global__ __launch_bounds__(256) void k_gemm1(const __half* __restrict__ A,
                                               const __half* __restrict__ Bt,
                                               __half* __restrict__ C,
                                               int M, int N, int K)
{
    extern __shared__ char dyn[];
    __half (*sA)[128][72] = (__half(*)[128][72])dyn;
    __half (*sB)[128][72] = (__half(*)[128][72])(dyn + 2 * 128 * 72 * 2);

    const int m0 = blockIdx.y * 128, n0 = blockIdx.x * 128;
    const int tid = threadIdx.x, warp = tid >> 5, lane = tid & 31;
    const int wm0 = (warp & 3) * 32;
    const int wn0 = (warp >> 2) * 64;
    const int g = lane >> 2, c2 = (lane & 3) * 2;

    const __half* Ag = A  + (size_t)m0 * K;
    const __half* Bg = Bt + (size_t)n0 * K;

    float acc[2][8][4];
    #pragma unroll
    for (int mt = 0; mt < 2; mt++)
        #pragma unroll
        for (int nt = 0; nt < 8; nt++)
            #pragma unroll
            for (int q = 0; q < 4; q++) acc[mt][nt][q] = 0.f;

    // ldmatrix per-lane address offsets (bytes) inside a 128x72 tile
    uint32_t aOff[2], bOff[4];
    #pragma unroll
    for (int mt = 0; mt < 2; mt++)
        aOff[mt] = ((wm0 + mt * 16 + (lane & 15)) * 72 + (lane >> 4) * 8) * 2;
    #pragma unroll
    for (int p = 0; p < 4; p++)
        bOff[p] = ((wn0 + p * 16 + ((lane >> 4) & 1) * 8 + (lane & 7)) * 72
                   + ((lane >> 3) & 1) * 8) * 2;
    const uint32_t sAb = cvta_s(sA), sBb = cvta_s(sB);
    const uint32_t stgA = 128 * 72 * 2;

    const int NC = K / 64;
    g1_issue(Ag, Bg, sA[0], sB[0], K, 0, tid);

    for (int kc = 0; kc < NC; kc++) {
        if (kc + 1 < NC) {
            g1_issue(Ag, Bg, sA[(kc + 1) & 1], sB[(kc + 1) & 1], K, (kc + 1) * 64, tid);
            asm volatile("cp.async.wait_group 1;\n" ::: "memory");
        } else {
            asm volatile("cp.async.wait_group 0;\n" ::: "memory");
        }
        __syncthreads();
        const uint32_t abase = sAb + (kc & 1) * stgA;
        const uint32_t bbase = sBb + (kc & 1) * stgA;
        #pragma unroll
        for (int kk = 0; kk < 64; kk += 16) {
            uint32_t af[2][4], bf[8][2];
            #pragma unroll
            for (int mt = 0; mt < 2; mt++)
                ldsm_x4(af[mt][0], af[mt][1], af[mt][2], af[mt][3],
                        abase + aOff[mt] + kk * 2);
            #pragma unroll
            for (int p = 0; p < 4; p++)
                ldsm_x4(bf[2*p][0], bf[2*p][1], bf[2*p+1][0], bf[2*p+1][1],
                        bbase + bOff[p] + kk * 2);
            #pragma unroll
            for (int mt = 0; mt < 2; mt++)
                #pragma unroll
                for (int nt = 0; nt < 8; nt++)
                    MMA16816(acc[mt][nt], af[mt], bf[nt][0], bf[nt][1]);
        }
        __syncthreads();
    }

    #pragma unroll
    for (int mt = 0; mt < 2; mt++) {
        int row = m0 + wm0 + mt * 16 + g;
        #pragma unroll
        for (int nt = 0; nt < 8; nt++) {
            int col = n0 + wn0 + nt * 8 + c2;
            *(__half2*)&C[(size_t)row       * N + col] = __floats2half2_rn(acc[mt][nt][0], acc[mt][nt][1]);
            *(__half2*)&C[(size_t)(row + 8) * N + col] = __floats2half2_rn(acc[mt][nt][2], acc[mt][nt][3]);
        }
    }
}

// ---------------- fused pairwise stage --------------------------------------
// One CTA = 128 rows x 256 feat. expand -> L2 -> L3 -> L4 -> column sum.
static const int SMEM_FUSED = 128*264*2 + 2*256*40*2 + 2*256*4;

__device__ __forceinline__ void prefetch_w(const __half* __restrict__ Wt, int kc,
                                           __half (*sWbuf)[40], int tid)
{
    #pragma unroll
    for (int it = 0; it < 4; it++) {
        int idx = it * 256 + tid;
        int n = idx >> 2, c4 = idx & 3;
        asm volatile("cp.async.cg.shared.global [%0], [%1], 16;\n"
                     :: "r"(cvta_s(&sWbuf[n][c4 * 8])), "l"(Wt + n * 256 + kc * 32 + c4 * 8));
    }
    asm volatile("cp.async.commit_group;\n");
}

__global__ __launch_bounds__(256, 1) void k_fused(const float* __restrict__ bg1,
                                                  const float* __restrict__ bg2,
                                                  const float* __restrict__ bg3,
                                                  const float* __restrict__ bg4)
{
    extern __shared__ char smem[];
    __half (*sAct)[264]   = (__half(*)[264])smem;
    __half (*sW)[256][40] = (__half(*)[256][40])(smem + 128*264*2);
    float*  sCol          = (float*)(smem + 128*264*2 + 2*256*40*2);

    const int tid  = threadIdx.x;
    const int warp = tid >> 5, lane = tid & 31;
    const int g    = lane >> 2, c2 = (lane & 3) * 2;
    const int wm0  = (warp & 1) * 64;
    const int wn0  = (warp >> 1) * 64;
    const int ct   = blockIdx.x;
    const int b    = ct >> 3;
    const int i0   = (ct & 7) * 4;

    const __half* wts[3]    = {g_w2t, g_w3t, g_w4t};
    const float*  biases[3] = {bg2, bg3, bg4};

    prefetch_w(wts[0], 0, sW[0], tid);

    // ---- build: act[m][d] = relu(A[b,j,d] + B[b,i,d] + bg1[d]) ----
    {
        int m = tid >> 1, half = tid & 1;
        int i = i0 + (m >> 5), j = m & 31;
        const __half2* Ar = (const __half2*)g_AB + (size_t)(b * 32 + j) * 256 + half * 64;
        const __half2* Br = (const __half2*)g_AB + (size_t)(b * 32 + i) * 256 + 128 + half * 64;
        const float2*  bb = (const float2*)bg1 + half * 64;
        __half2* dst = (__half2*)&sAct[m][half * 128];
        #pragma unroll 8
        for (int cc = 0; cc < 64; cc++) {
            float2 a = __half22float2(Ar[cc]);
            float2 e = __half22float2(Br[cc]);
            float2 bi = bb[cc];
            dst[cc] = __floats2half2_rn(fmaxf(a.x + e.x + bi.x, 0.f),
                                        fmaxf(a.y + e.y + bi.y, 0.f));
        }
    }

    // ldmatrix lane-address offsets
    uint32_t aAddr[4], bOff[4];
    #pragma unroll
    for (int mt = 0; mt < 4; mt++)
        aAddr[mt] = cvta_s(&sAct[wm0 + mt * 16 + (lane & 15)][(lane >> 4) * 8]);
    #pragma unroll
    for (int p = 0; p < 4; p++)
        bOff[p] = ((wn0 + p * 16 + ((lane >> 4) & 1) * 8 + (lane & 7)) * 40
                   + ((lane >> 3) & 1) * 8) * 2;
    const uint32_t sWb = cvta_s(sW);
    const uint32_t wBufSz = 256 * 40 * 2;

    for (int L = 0; L < 3; L++) {
        const __half* Wt  = wts[L];
        const float* bias = biases[L];

        float acc[4][8][4];
        #pragma unroll
        for (int mt = 0; mt < 4; mt++)
            #pragma unroll
            for (int nt = 0; nt < 8; nt++)
                #pragma unroll
                for (int q = 0; q < 4; q++) acc[mt][nt][q] = 0.f;

        for (int kc = 0; kc < 8; kc++) {
            asm volatile("cp.async.wait_group 0;\n" ::: "memory");
            __syncthreads();
            if (kc < 7)     prefetch_w(Wt,       kc + 1, sW[(kc + 1) & 1], tid);
            else if (L < 2) prefetch_w(wts[L+1], 0,      sW[0],            tid);
            const uint32_t bbase = sWb + (kc & 1) * wBufSz;

            #pragma unroll
            for (int kk = 0; kk < 32; kk += 16) {
                const int kbase = kc * 32 + kk;
                uint32_t af[4][4], bf[8][2];
                #pragma unroll
                for (int mt = 0; mt < 4; mt++)
                    ldsm_x4(af[mt][0], af[mt][1], af[mt][2], af[mt][3],
                            aAddr[mt] + kbase * 2);
                #pragma unroll
                for (int p = 0; p < 4; p++)
                    ldsm_x4(bf[2*p][0], bf[2*p][1], bf[2*p+1][0], bf[2*p+1][1],
                            bbase + bOff[p] + kk * 2);
                #pragma unroll
                for (int mt = 0; mt < 4; mt++)
                    #pragma unroll
                    for (int nt = 0; nt < 8; nt++)
                        MMA16816(acc[mt][nt], af[mt], bf[nt][0], bf[nt][1]);
            }
        }
        __syncthreads();   // all warps done reading sAct for this layer

        if (L < 2) {
            #pragma unroll
            for (int mt = 0; mt < 4; mt++) {
                int row = wm0 + mt * 16 + g;
                #pragma unroll
                for (int nt = 0; nt < 8; nt++) {
                    int col = wn0 + nt * 8 + c2;
                    float b0 = bias[col], b1 = bias[col + 1];
                    *(__half2*)&sAct[row    ][col] =
                        __floats2half2_rn(fmaxf(acc[mt][nt][0] + b0, 0.f),
                                          fmaxf(acc[mt][nt][1] + b1, 0.f));
                    *(__half2*)&sAct[row + 8][col] =
                        __floats2half2_rn(fmaxf(acc[mt][nt][2] + b0, 0.f),
                                          fmaxf(acc[mt][nt][3] + b1, 0.f));
                }
            }
        } else {
            #pragma unroll
            for (int nt = 0; nt < 8; nt++) {
                int col = wn0 + nt * 8 + c2;
                float b0 = bias[col], b1 = bias[col + 1];
                float s0 = 0.f, s1 = 0.f;
                #pragma unroll
                for (int mt = 0; mt < 4; mt++) {
                    s0 += fmaxf(acc[mt][nt][0] + b0, 0.f) + fmaxf(acc[mt][nt][2] + b0, 0.f);
                    s1 += fmaxf(acc[mt][nt][1] + b1, 0.f) + fmaxf(acc[mt][nt][3] + b1, 0.f);
                }
                #pragma unroll
                for (int o = 4; o < 32; o <<= 1) {
                    s0 += __shfl_xor_sync(0xffffffffu, s0, o);
                    s1 += __shfl_xor_sync(0xffffffffu, s1, o);
                }
                if (lane < 4) {
                    sCol[(warp & 1) * 256 + wn0 + nt * 8 + lane * 2    ] = s0;
                    sCol[(warp & 1) * 256 + wn0 + nt * 8 + lane * 2 + 1] = s1;
                }
            }
            __syncthreads();
            g_part[(size_t)ct * 256 + tid] = sCol[tid] + sCol[256 + tid];
        }
    }
}

// ---------------- tails (128 rows, fp32) ------------------------------------
// tail1: xg = sum of 8 partials, then relu(xg @ Wf1 + bf1) -> g_xf
__global__ void k_tail1(const float* __restrict__ W, const float* __restrict__ bias)
{
    __shared__ float sx[256];
    int b = blockIdx.x, n = threadIdx.x;
    float a = 0.f;
    #pragma unroll
    for (int s = 0; s < 8; s++) a += g_part[(size_t)(b * 8 + s) * 256 + n];
    sx[n] = a;
    __syncthreads();
    float acc = bias[n];
    for (int k = 0; k < 256; k++) acc = fmaf(sx[k], W[(size_t)k * 256 + n], acc);
    g_xf[(size_t)b * 256 + n] = fmaxf(acc, 0.f);
}

template<int RELU>
__global__ void k_tail(const float* __restrict__ X, const float* __restrict__ W,
                       const float* __restrict__ bias, float* __restrict__ Y,
                       int K, int N)
{
    __shared__ float sx[256];
    int row = blockIdx.x, n = threadIdx.x;
    for (int k = n; k < K; k += blockDim.x) sx[k] = X[(size_t)row * K + k];
    __syncthreads();
    float acc = bias[n];
    for (int k = 0; k < K; k++) acc = fmaf(sx[k], W[(size_t)k * N + n], acc);
    if (RELU) acc = fmaxf(acc, 0.f);
    Y[(size_t)row * N + n] = acc;
}

// ---------------- host ------------------------------------------------------
extern "C" void kernel_launch(void* const* d_in, const int* in_sizes, int n_in,
                              void* d_out, int out_size)
{
    const float* x    = (const float*)d_in[0];
    const float* Wg1  = (const float*)d_in[1];
    const float* bg1  = (const float*)d_in[2];
    const float* Wg2  = (const float*)d_in[3];
    const float* bg2  = (const float*)d_in[4];
    const float* Wg3  = (const float*)d_in[5];
    const float* bg3  = (const float*)d_in[6];
    const float* Wg4  = (const float*)d_in[7];
    const float* bg4  = (const float*)d_in[8];
    const float* Wf1  = (const float*)d_in[9];
    const float* bf1  = (const float*)d_in[10];
    const float* Wfc2 = (const float*)d_in[11];
    const float* bfc2 = (const float*)d_in[12];
    const float* Wfc3 = (const float*)d_in[13];
    const float* bfc3 = (const float*)d_in[14];
    float* out = (float*)d_out;

    __half *xh, *w1t, *AB;
    float *xf, *y1;
    cudaGetSymbolAddress((void**)&xh,  g_xh);
    cudaGetSymbolAddress((void**)&w1t, g_w1t);
    cudaGetSymbolAddress((void**)&AB,  g_AB);
    cudaGetSymbolAddress((void**)&xf,  g_xf);
    cudaGetSymbolAddress((void**)&y1,  g_y1);

    cudaFuncSetAttribute(k_fused, cudaFuncAttributeMaxDynamicSharedMemorySize, SMEM_FUSED);
    cudaFuncSetAttribute(k_gemm1, cudaFuncAttributeMaxDynamicSharedMemorySize, G1_SMEM);

    dim3 tb(32, 8);
    k_transpose<<<dim3(1, 64, 128), tb>>>(x, xh, 2048, 32);                     // 1
    k_transpose<<<dim3(8, 64, 1), tb>>>(Wg1,              w1t,              2048, 256); // 2
    k_transpose<<<dim3(8, 64, 1), tb>>>(Wg1 + 2048 * 256, w1t + 256 * 2048, 2048, 256); // 3
    k_gemm1<<<dim3(4, 32), 256, G1_SMEM>>>(xh, w1t, AB, 4096, 512, 2048);       // 4
    k_transpose_w234<<<dim3(8, 8, 3), tb>>>(Wg2, Wg3, Wg4);                     // 5
    k_fused<<<1024, 256, SMEM_FUSED>>>(bg1, bg2, bg3, bg4);                     // 6 (profiled)
    k_tail1<<<128, 256>>>(Wf1, bf1);                                            // 7
    k_tail<1><<<128, 256>>>(xf, Wfc2, bfc2, y1,  256, 256);                     // 8
    k_tail<0><<<128, 128>>>(y1, Wfc3, bfc3, out, 256, 128);                     // 9
}